// round 15
// baseline (speedup 1.0000x reference)
#include <cuda_runtime.h>
#include <math.h>

#define Bb   128
#define Tt   512
#define Hh   256
#define Cc   20
#define BT   (Bb*Tt)          // 65536

typedef unsigned long long ull;

// ---------------------------------------------------------------------------
// Scratch (device globals; allocation-free)
// ---------------------------------------------------------------------------
__device__ float g_x0[(size_t)BT * 256];              //  64 MB embeddings
__device__ float g_xg[(size_t)2 * BT * 1024];         // 512 MB input projections [dir][bt][1024]
__device__ float g_h0[(size_t)BT * 512];              // 128 MB layer0 output
__device__ float g_h1[(size_t)BT * 512];              // 128 MB layer1 output
__device__ float g_hbuf[2 * Bb * Hh];                 // h spill at scan split [dir][b][u]
__device__ float g_cst[2 * Bb * Hh];                  // c spill at scan split [dir][b][u]
__device__ float g_bias0[2 * 1024];
__device__ float g_bias1[2 * 1024];
__device__ float g_em[(size_t)BT * Cc];               // emissions
__device__ float g_lossb[Bb];

__device__ __forceinline__ float sigf(float x) { return 1.0f / (1.0f + __expf(-x)); }

__device__ __forceinline__ void ffma2(ull& d, ull a, ull b)
{
    asm("fma.rn.f32x2 %0, %1, %2, %0;" : "+l"(d) : "l"(a), "l"(b));
}
__device__ __forceinline__ float2 unpack2(ull v)
{
    float2 f;
    asm("mov.b64 {%0, %1}, %2;" : "=f"(f.x), "=f"(f.y) : "l"(v));
    return f;
}
__device__ __forceinline__ float rsum2(ull v) { float2 f = unpack2(v); return f.x + f.y; }
__device__ __forceinline__ ull pack2s(float b)
{
    ull r;
    asm("mov.b64 %0, {%1, %1};" : "=l"(r) : "f"(b));
    return r;
}
__device__ __forceinline__ unsigned smem_u32(const void* p)
{
    unsigned a;
    asm("{ .reg .u64 t; cvta.to.shared.u64 t, %1; cvt.u32.u64 %0, t; }"
        : "=r"(a) : "l"(p));
    return a;
}

// ---------------------------------------------------------------------------
// bias combine (idempotent; also used as filler for ncu alignment)
// ---------------------------------------------------------------------------
__global__ void k_bias(const float* __restrict__ bi0, const float* __restrict__ bh0,
                       const float* __restrict__ bi1, const float* __restrict__ bh1)
{
    int i = blockIdx.x * 256 + threadIdx.x;
    if (i < 2048) {
        g_bias0[i] = bi0[i] + bh0[i];
        g_bias1[i] = bi1[i] + bh1[i];
    }
}

// ---------------------------------------------------------------------------
// embedding gather (float4)
// ---------------------------------------------------------------------------
__global__ void k_embed(const int* __restrict__ ids, const float* __restrict__ emb)
{
    int g  = blockIdx.x * 256 + threadIdx.x;   // 0 .. BT*64-1
    int bt = g >> 6;
    int e4 = g & 63;
    int id = __ldg(ids + bt);
    ((float4*)g_x0)[g] = ((const float4*)emb)[(size_t)id * 64 + e4];
}

// ---------------------------------------------------------------------------
// Input projection SGEMM v3 (f32x2, double-buffered, 128x128 tile) — unchanged
// ---------------------------------------------------------------------------
#define PA 132
#define PB 132
__global__ void __launch_bounds__(256) k_gemm(int layer, int z, const float* __restrict__ Wall)
{
    const float* A    = layer ? g_h0    : g_x0;
    const float* bias = layer ? g_bias1 : g_bias0;
    const int    K    = layer ? 512 : 256;
    const int    KT   = K >> 4;

    const float* W  = Wall + (size_t)z * 1024 * K;
    const float* bz = bias + z * 1024;
    float*       C  = g_xg + (size_t)z * BT * 1024;

    int n0 = blockIdx.x * 128;
    int m0 = blockIdx.y * 128;

    __shared__ __align__(16) float As[2][16 * PA];
    __shared__ __align__(16) float Bs[2][16 * PB];

    int tid = threadIdx.x;
    int tx = tid & 15, ty = tid >> 4;
    int mm = ty * 8, nn = tx * 8;

    int row0 = tid >> 2,          kq = tid & 3;
    int row1 = (tid + 256) >> 2;

    ull acc2[4][8];
#pragma unroll
    for (int i = 0; i < 4; i++)
#pragma unroll
        for (int j = 0; j < 8; j++) acc2[i][j] = 0ull;

    float4 pa0 = *(const float4*)(A + (size_t)(m0 + row0) * K + kq * 4);
    float4 pa1 = *(const float4*)(A + (size_t)(m0 + row1) * K + kq * 4);
    float4 pb0 = *(const float4*)(W + (size_t)(n0 + row0) * K + kq * 4);
    float4 pb1 = *(const float4*)(W + (size_t)(n0 + row1) * K + kq * 4);
    {
        float* asb = As[0];
        asb[(kq * 4 + 0) * PA + row0] = pa0.x;
        asb[(kq * 4 + 1) * PA + row0] = pa0.y;
        asb[(kq * 4 + 2) * PA + row0] = pa0.z;
        asb[(kq * 4 + 3) * PA + row0] = pa0.w;
        asb[(kq * 4 + 0) * PA + row1] = pa1.x;
        asb[(kq * 4 + 1) * PA + row1] = pa1.y;
        asb[(kq * 4 + 2) * PA + row1] = pa1.z;
        asb[(kq * 4 + 3) * PA + row1] = pa1.w;
        float* bsb = Bs[0];
        bsb[(kq * 4 + 0) * PB + row0] = pb0.x;
        bsb[(kq * 4 + 1) * PB + row0] = pb0.y;
        bsb[(kq * 4 + 2) * PB + row0] = pb0.z;
        bsb[(kq * 4 + 3) * PB + row0] = pb0.w;
        bsb[(kq * 4 + 0) * PB + row1] = pb1.x;
        bsb[(kq * 4 + 1) * PB + row1] = pb1.y;
        bsb[(kq * 4 + 2) * PB + row1] = pb1.z;
        bsb[(kq * 4 + 3) * PB + row1] = pb1.w;
    }
    __syncthreads();

    for (int kt = 0; kt < KT; kt++) {
        int cur = kt & 1;
        if (kt + 1 < KT) {
            int kof = (kt + 1) * 16;
            pa0 = *(const float4*)(A + (size_t)(m0 + row0) * K + kof + kq * 4);
            pa1 = *(const float4*)(A + (size_t)(m0 + row1) * K + kof + kq * 4);
            pb0 = *(const float4*)(W + (size_t)(n0 + row0) * K + kof + kq * 4);
            pb1 = *(const float4*)(W + (size_t)(n0 + row1) * K + kof + kq * 4);
        }
        const float* asb = As[cur];
        const float* bsb = Bs[cur];
#pragma unroll
        for (int k = 0; k < 16; k++) {
            ulonglong2 a01 = *(const ulonglong2*)(asb + k * PA + mm);
            ulonglong2 a23 = *(const ulonglong2*)(asb + k * PA + mm + 4);
            float4 b0 = *(const float4*)(bsb + k * PB + nn);
            float4 b1 = *(const float4*)(bsb + k * PB + nn + 4);
            ull av[4] = {a01.x, a01.y, a23.x, a23.y};
            ull bb[8] = {pack2s(b0.x), pack2s(b0.y), pack2s(b0.z), pack2s(b0.w),
                         pack2s(b1.x), pack2s(b1.y), pack2s(b1.z), pack2s(b1.w)};
#pragma unroll
            for (int i = 0; i < 4; i++)
#pragma unroll
                for (int j = 0; j < 8; j++) ffma2(acc2[i][j], av[i], bb[j]);
        }
        if (kt + 1 < KT) {
            float* asn = As[cur ^ 1];
            asn[(kq * 4 + 0) * PA + row0] = pa0.x;
            asn[(kq * 4 + 1) * PA + row0] = pa0.y;
            asn[(kq * 4 + 2) * PA + row0] = pa0.z;
            asn[(kq * 4 + 3) * PA + row0] = pa0.w;
            asn[(kq * 4 + 0) * PA + row1] = pa1.x;
            asn[(kq * 4 + 1) * PA + row1] = pa1.y;
            asn[(kq * 4 + 2) * PA + row1] = pa1.z;
            asn[(kq * 4 + 3) * PA + row1] = pa1.w;
            float* bsn = Bs[cur ^ 1];
            bsn[(kq * 4 + 0) * PB + row0] = pb0.x;
            bsn[(kq * 4 + 1) * PB + row0] = pb0.y;
            bsn[(kq * 4 + 2) * PB + row0] = pb0.z;
            bsn[(kq * 4 + 3) * PB + row0] = pb0.w;
            bsn[(kq * 4 + 0) * PB + row1] = pb1.x;
            bsn[(kq * 4 + 1) * PB + row1] = pb1.y;
            bsn[(kq * 4 + 2) * PB + row1] = pb1.z;
            bsn[(kq * 4 + 3) * PB + row1] = pb1.w;
            __syncthreads();
        }
    }

    float4 bvx0 = *(const float4*)(bz + n0 + nn);
    float4 bvx1 = *(const float4*)(bz + n0 + nn + 4);
#pragma unroll
    for (int ip = 0; ip < 4; ip++) {
        float2 c0 = unpack2(acc2[ip][0]);
        float2 c1 = unpack2(acc2[ip][1]);
        float2 c2 = unpack2(acc2[ip][2]);
        float2 c3 = unpack2(acc2[ip][3]);
        float2 c4 = unpack2(acc2[ip][4]);
        float2 c5 = unpack2(acc2[ip][5]);
        float2 c6 = unpack2(acc2[ip][6]);
        float2 c7 = unpack2(acc2[ip][7]);
        float* r0 = C + (size_t)(m0 + mm + 2 * ip) * 1024 + n0 + nn;
        float* r1 = C + (size_t)(m0 + mm + 2 * ip + 1) * 1024 + n0 + nn;
        float4 oa = {c0.x + bvx0.x, c1.x + bvx0.y, c2.x + bvx0.z, c3.x + bvx0.w};
        float4 ob = {c4.x + bvx1.x, c5.x + bvx1.y, c6.x + bvx1.z, c7.x + bvx1.w};
        *(float4*)(r0) = oa;
        *(float4*)(r0 + 4) = ob;
        float4 oc = {c0.y + bvx0.x, c1.y + bvx0.y, c2.y + bvx0.z, c3.y + bvx0.w};
        float4 od = {c4.y + bvx1.x, c5.y + bvx1.y, c6.y + bvx1.z, c7.y + bvx1.w};
        *(float4*)(r1) = oc;
        *(float4*)(r1 + 4) = od;
    }
}

// ---------------------------------------------------------------------------
// Persistent BiLSTM scan v6 — 8-CTA clusters with DSMEM h-exchange.
//   128 blocks x 512 threads, 1 block/SM. blk = dir*64 + btile*8 + utile;
//   cluster = the 8 u-tile blocks of one (dir,btile) group (rank = utile).
//   smem: w_hh slice [4g x 32u][256k] (130KB) + double-buffered h staging
//   hs[2][16b][260] + k-partial exchange red (32KB) = 199KB.
//   Per step: compute from LOCAL hs -> k-reduce via red -> epilogue (c in reg)
//   -> push h cell to all 8 CTAs' hs[next] via st.shared::cluster
//   -> cluster arrive (release) -> hout store + xg prefetch in shadow -> wait.
//   No L2 publish/poll, no staging reads, no software barrier state.
//   Runs steps [t0,t1); c/h spilled to g_cst/g_hbuf at a split boundary.
// ---------------------------------------------------------------------------
#define KP 260
#define WS_OFF 0
#define HS_OFF (128 * KP)                 // 33280 floats
#define RED_OFF (HS_OFF + 2 * 16 * KP)    // + 8320 floats
#define SCAN_SMEM_FLOATS (RED_OFF + 8192) // 49792 floats = 199168 B

__global__ void __launch_bounds__(512, 1) __cluster_dims__(8, 1, 1)
k_scan(int layer, int t0, int t1, const float* __restrict__ Whh_all)
{
    extern __shared__ float sm[];
    float* ws  = sm + WS_OFF;
    float* red = sm + RED_OFF;

    float* hout = layer ? g_h1 : g_h0;
    int blk = blockIdx.x;
    int dir = blk >> 6;
    int rem = blk & 63;
    int bt  = rem >> 3;                // b-tile 0..7
    int ut  = rem & 7;                 // u-tile = cluster rank
    int u0  = ut * 32;
    int b0  = bt * 16;

    int tid = threadIdx.x;
    int ul = tid & 31;                 // unit within tile
    int bq = (tid >> 5) & 3;           // 4-batch group
    int ks = tid >> 7;                 // k quarter (64 k)
    int bo = tid >> 5;                 // 0..15 epilogue batch row (= ks*4+bq)
    int u  = u0 + ul;
    int bcell = b0 + bo;

    // stage w_hh slice: rows = 4g x 32u, 256 k each
    const float4* W4 = (const float4*)(Whh_all + (size_t)dir * 1024 * 256);
    for (int i = tid; i < 8192; i += 512) {
        int row = i >> 6, k4 = i & 63;
        int g = row >> 5, uu = row & 31;
        int j = g * 256 + u0 + uu;
        *(float4*)(ws + row * KP + k4 * 4) = W4[(size_t)j * 64 + k4];
    }

    float creg = 0.f;
    if (t0 > 0) {
        creg = g_cst[((size_t)dir * Bb + bcell) * Hh + u];
        // prestage hs[t0&1] with h(t0-1) from the spill
        float* hsp = sm + HS_OFF + (t0 & 1) * (16 * KP);
        const float4* HB4 = (const float4*)g_hbuf;
        for (int i = tid; i < 1024; i += 512) {
            int b = i >> 6, k4 = i & 63;
            float4 v = __ldcg(HB4 + ((size_t)dir * Bb + b0 + b) * 64 + k4);
            *(float4*)(hsp + b * KP + k4 * 4) = v;
        }
    }

    // xg gates for t0
    float xpre[4];
    {
        int ta = dir ? (511 - t0) : t0;
        const float* xr = g_xg + ((size_t)dir * BT + (size_t)bcell * 512 + ta) * 1024;
        xpre[0] = __ldcs(xr + u);
        xpre[1] = __ldcs(xr + 256 + u);
        xpre[2] = __ldcs(xr + 512 + u);
        xpre[3] = __ldcs(xr + 768 + u);
    }
    __syncthreads();
    // cluster-wide: everyone staged before any DSMEM pushes arrive
    asm volatile("barrier.cluster.arrive.aligned;" ::: "memory");
    asm volatile("barrier.cluster.wait.aligned;" ::: "memory");

    unsigned smbase = smem_u32(sm);

    for (int t = t0; t < t1; t++) {
        int t_act = dir ? (511 - t) : t;
        const float* hs_cur = sm + HS_OFF + (t & 1) * (16 * KP);
        unsigned hs_nxt_u32 = smbase + (HS_OFF + ((t + 1) & 1) * (16 * KP)) * 4;

        ull acc2[4][4];
#pragma unroll
        for (int g = 0; g < 4; g++)
#pragma unroll
            for (int i = 0; i < 4; i++) acc2[g][i] = 0ull;

        if (t > 0) {
#pragma unroll 8
            for (int kq = 0; kq < 16; kq++) {
                int ko = ks * 64 + kq * 4;
                ulonglong2 wv[4], hv[4];
#pragma unroll
                for (int g = 0; g < 4; g++)
                    wv[g] = *(const ulonglong2*)(ws + (g * 32 + ul) * KP + ko);
#pragma unroll
                for (int i = 0; i < 4; i++)
                    hv[i] = *(const ulonglong2*)(hs_cur + (bq * 4 + i) * KP + ko);
#pragma unroll
                for (int g = 0; g < 4; g++)
#pragma unroll
                    for (int i = 0; i < 4; i++) {
                        ffma2(acc2[g][i], hv[i].x, wv[g].x);
                        ffma2(acc2[g][i], hv[i].y, wv[g].y);
                    }
            }
        }

        // k-partial exchange: red[ks][g][b][ul]
#pragma unroll
        for (int g = 0; g < 4; g++)
#pragma unroll
            for (int i = 0; i < 4; i++)
                red[((ks * 4 + g) * 16 + bq * 4 + i) * 32 + ul] = rsum2(acc2[g][i]);
        __syncthreads();

        // epilogue: this thread's cell (bcell, u)
        float h;
        {
            float gate[4];
#pragma unroll
            for (int g = 0; g < 4; g++) {
                float s = xpre[g];
#pragma unroll
                for (int k = 0; k < 4; k++)
                    s += red[((k * 4 + g) * 16 + bo) * 32 + ul];
                gate[g] = s;
            }
            float c = sigf(gate[1]) * creg + sigf(gate[0]) * tanhf(gate[2]);
            creg = c;
            h = sigf(gate[3]) * tanhf(c);
        }
        size_t btx = (size_t)bcell * 512 + t_act;

        if (t < t1 - 1) {
            // push h into all 8 cluster CTAs' hs[next] (incl. self)
            unsigned off = hs_nxt_u32 + (unsigned)(bo * KP + u) * 4u;
#pragma unroll
            for (int r = 0; r < 8; r++) {
                unsigned ra;
                asm("mapa.shared::cluster.u32 %0, %1, %2;" : "=r"(ra) : "r"(off), "r"(r));
                asm volatile("st.shared::cluster.f32 [%0], %1;" :: "r"(ra), "f"(h) : "memory");
            }
            asm volatile("barrier.cluster.arrive.aligned;" ::: "memory");
            // barrier shadow: hout store + next xg prefetch
            __stcs(hout + btx * 512 + dir * 256 + u, h);
            {
                int tn = dir ? (510 - t) : (t + 1);
                const float* xr = g_xg + ((size_t)dir * BT + (size_t)bcell * 512 + tn) * 1024;
                xpre[0] = __ldcs(xr + u);
                xpre[1] = __ldcs(xr + 256 + u);
                xpre[2] = __ldcs(xr + 512 + u);
                xpre[3] = __ldcs(xr + 768 + u);
            }
            asm volatile("barrier.cluster.wait.aligned;" ::: "memory");
        } else {
            __stcs(hout + btx * 512 + dir * 256 + u, h);
            if (t1 < 512) {   // split boundary: spill c and h
                g_cst [((size_t)dir * Bb + bcell) * Hh + u] = creg;
                g_hbuf[((size_t)dir * Bb + bcell) * Hh + u] = h;
            }
        }
    }

    // DSMEM lifetime safety
    asm volatile("barrier.cluster.arrive.aligned;" ::: "memory");
    asm volatile("barrier.cluster.wait.aligned;" ::: "memory");
}

// ---------------------------------------------------------------------------
// Emissions
// ---------------------------------------------------------------------------
#define PWE 68
__global__ void __launch_bounds__(256) k_emis(const float* __restrict__ fcw,
                                              const float* __restrict__ fcb)
{
    __shared__ __align__(16) float hsm[8 * 512];
    __shared__ __align__(16) float wsm[20 * PWE];

    int bt0 = blockIdx.x * 8;
    int tid = threadIdx.x;

    const float4* H4 = (const float4*)g_h1;
#pragma unroll
    for (int i = tid; i < 1024; i += 256) {
        int r = i >> 7, k4 = i & 127;
        ((float4*)hsm)[r * 128 + k4] = H4[(size_t)(bt0 + r) * 128 + k4];
    }

    int r = tid / 20, c = tid % 20;
    bool act = (tid < 160);
    float acc = 0.f;

    const float4* W4 = (const float4*)fcw;
    for (int cc = 0; cc < 8; cc++) {
        __syncthreads();
        for (int i = tid; i < 320; i += 256) {
            int cw = i >> 4, k4 = i & 15;
            *(float4*)(wsm + cw * PWE + k4 * 4) = W4[(size_t)cw * 128 + cc * 16 + k4];
        }
        __syncthreads();
        if (act) {
#pragma unroll
            for (int k4 = 0; k4 < 16; k4++) {
                float4 h4 = ((const float4*)hsm)[r * 128 + cc * 16 + k4];
                float4 w4 = *(const float4*)(wsm + c * PWE + k4 * 4);
                acc += h4.x * w4.x + h4.y * w4.y + h4.z * w4.z + h4.w * w4.w;
            }
        }
    }
    if (act)
        g_em[(size_t)(bt0 + r) * Cc + c] = acc + __ldg(fcb + c);
}

// ---------------------------------------------------------------------------
// CRF NLL per batch: one warp per batch row.
// ---------------------------------------------------------------------------
__global__ void __launch_bounds__(32) k_crf(const int* __restrict__ labels,
                                            const float* __restrict__ trans,
                                            const float* __restrict__ start,
                                            const float* __restrict__ endt)
{
    int b = blockIdx.x;
    int lane = threadIdx.x;
    const float* em = g_em + (size_t)b * Tt * Cc;
    const int* tag = labels + (size_t)b * Tt;

    float part = 0.f;
    for (int t = lane; t < Tt; t += 32) {
        int tg = __ldg(tag + t);
        part += em[(size_t)t * Cc + tg];
        if (t < Tt - 1) part += __ldg(trans + tg * Cc + __ldg(tag + t + 1));
    }
#pragma unroll
    for (int o = 16; o; o >>= 1) part += __shfl_xor_sync(0xFFFFFFFFu, part, o);
    float num = part;

    int j = lane;
    bool act = (j < Cc);
    float tc[Cc];
#pragma unroll
    for (int i = 0; i < Cc; i++) tc[i] = act ? __ldg(trans + i * Cc + j) : 0.f;

    float alpha = act ? (__ldg(start + j) + em[j]) : -1e30f;
    for (int t = 1; t < Tt; t++) {
        float v[Cc];
        float m = -1e30f;
#pragma unroll
        for (int i = 0; i < Cc; i++) {
            v[i] = __shfl_sync(0xFFFFFFFFu, alpha, i) + tc[i];
            m = fmaxf(m, v[i]);
        }
        float s = 0.f;
#pragma unroll
        for (int i = 0; i < Cc; i++) s += __expf(v[i] - m);
        float e = act ? em[(size_t)t * Cc + j] : 0.f;
        alpha = act ? (m + __logf(s) + e) : -1e30f;
    }

    float av = act ? (alpha + __ldg(endt + j)) : -1e30f;
    float mm = av;
#pragma unroll
    for (int o = 16; o; o >>= 1) mm = fmaxf(mm, __shfl_xor_sync(0xFFFFFFFFu, mm, o));
    float ss = act ? __expf(av - mm) : 0.f;
#pragma unroll
    for (int o = 16; o; o >>= 1) ss += __shfl_xor_sync(0xFFFFFFFFu, ss, o);
    float logZ = mm + __logf(ss);

    if (lane == 0) {
        float g0 = __ldg(start + __ldg(tag + 0)) + __ldg(endt + __ldg(tag + Tt - 1));
        g_lossb[b] = (num + g0) - logZ;
    }
}

// ---------------------------------------------------------------------------
// Final deterministic reduce
// ---------------------------------------------------------------------------
__global__ void k_reduce(float* __restrict__ out)
{
    __shared__ float s[128];
    s[threadIdx.x] = g_lossb[threadIdx.x];
    __syncthreads();
#pragma unroll
    for (int o = 64; o; o >>= 1) {
        if (threadIdx.x < o) s[threadIdx.x] += s[threadIdx.x + o];
        __syncthreads();
    }
    if (threadIdx.x == 0) out[0] = -s[0];
}

// ---------------------------------------------------------------------------
// kernel_launch — 15 nodes; launch #7 = k_scan(L0, first half) for ncu
// ---------------------------------------------------------------------------
extern "C" void kernel_launch(void* const* d_in, const int* in_sizes, int n_in,
                              void* d_out, int out_size)
{
    const int*   ids      = (const int*)d_in[0];
    const int*   labels   = (const int*)d_in[1];
    const float* emb      = (const float*)d_in[2];
    const float* w_ih_l0  = (const float*)d_in[3];
    const float* w_hh_l0  = (const float*)d_in[4];
    const float* b_ih_l0  = (const float*)d_in[5];
    const float* b_hh_l0  = (const float*)d_in[6];
    const float* w_ih_l1  = (const float*)d_in[7];
    const float* w_hh_l1  = (const float*)d_in[8];
    const float* b_ih_l1  = (const float*)d_in[9];
    const float* b_hh_l1  = (const float*)d_in[10];
    const float* fc_w     = (const float*)d_in[11];
    const float* fc_b     = (const float*)d_in[12];
    const float* trans    = (const float*)d_in[13];
    const float* start    = (const float*)d_in[14];
    const float* endt     = (const float*)d_in[15];

    const int scan_smem = SCAN_SMEM_FLOATS * (int)sizeof(float);   // 199168 B
    cudaFuncSetAttribute(k_scan, cudaFuncAttributeMaxDynamicSharedMemorySize, scan_smem);

    k_bias<<<8, 256>>>(b_ih_l0, b_hh_l0, b_ih_l1, b_hh_l1);        // 1
    k_embed<<<16384, 256>>>(ids, emb);                              // 2
    k_bias<<<8, 256>>>(b_ih_l0, b_hh_l0, b_ih_l1, b_hh_l1);        // 3 (filler)
    k_bias<<<8, 256>>>(b_ih_l0, b_hh_l0, b_ih_l1, b_hh_l1);        // 4 (filler)

    // layer 0
    k_gemm<<<dim3(8, 512), 256>>>(0, 0, w_ih_l0);                   // 5
    k_gemm<<<dim3(8, 512), 256>>>(0, 1, w_ih_l0);                   // 6
    k_scan<<<128, 512, scan_smem>>>(0, 0, 256, w_hh_l0);            // 7  <- profiled
    k_scan<<<128, 512, scan_smem>>>(0, 256, 512, w_hh_l0);          // 8

    // layer 1
    k_gemm<<<dim3(8, 512), 256>>>(1, 0, w_ih_l1);                   // 9
    k_gemm<<<dim3(8, 512), 256>>>(1, 1, w_ih_l1);                   // 10
    k_scan<<<128, 512, scan_smem>>>(1, 0, 256, w_hh_l1);            // 11
    k_scan<<<128, 512, scan_smem>>>(1, 256, 512, w_hh_l1);          // 12

    k_emis<<<BT / 8, 256>>>(fc_w, fc_b);                            // 13
    k_crf<<<Bb, 32>>>(labels, trans, start, endt);                  // 14
    k_reduce<<<1, 128>>>((float*)d_out);                            // 15
}

// round 16
// speedup vs baseline: 1.2221x; 1.2221x over previous
#include <cuda_runtime.h>
#include <math.h>

#define Bb   128
#define Tt   512
#define Hh   256
#define Cc   20
#define BT   (Bb*Tt)          // 65536

typedef unsigned long long ull;

// ---------------------------------------------------------------------------
// Scratch (device globals; allocation-free)
// ---------------------------------------------------------------------------
__device__ float g_x0[(size_t)BT * 256];              //  64 MB embeddings
__device__ float g_xg[(size_t)2 * BT * 1024];         // 512 MB input projections [dir][bt][1024]
__device__ float g_h0[(size_t)BT * 512];              // 128 MB layer0 output
__device__ float g_h1[(size_t)BT * 512];              // 128 MB layer1 output
__device__ float g_hbuf[2 * 2 * Bb * Hh];             // h ping-pong [dir][pp][b][u]
__device__ float g_bias0[2 * 1024];
__device__ float g_bias1[2 * 1024];
__device__ float g_em[(size_t)BT * Cc];               // emissions
__device__ float g_lossb[Bb];
__device__ unsigned g_flag[1024];                     // [8 grp][16 prod] x 8-word pad

__device__ __forceinline__ float sigf(float x) { return 1.0f / (1.0f + __expf(-x)); }

__device__ __forceinline__ void ffma2(ull& d, ull a, ull b)
{
    asm("fma.rn.f32x2 %0, %1, %2, %0;" : "+l"(d) : "l"(a), "l"(b));
}
__device__ __forceinline__ float2 unpack2(ull v)
{
    float2 f;
    asm("mov.b64 {%0, %1}, %2;" : "=f"(f.x), "=f"(f.y) : "l"(v));
    return f;
}
__device__ __forceinline__ float rsum2(ull v) { float2 f = unpack2(v); return f.x + f.y; }
__device__ __forceinline__ ull pack2s(float b)
{
    ull r;
    asm("mov.b64 %0, {%1, %1};" : "=l"(r) : "f"(b));
    return r;
}
__device__ __forceinline__ void st_release(unsigned* p, unsigned v)
{
    asm volatile("st.release.gpu.u32 [%0], %1;" :: "l"(p), "r"(v) : "memory");
}
__device__ __forceinline__ unsigned ld_acquire(unsigned* p)
{
    unsigned v;
    asm volatile("ld.acquire.gpu.u32 %0, [%1];" : "=r"(v) : "l"(p) : "memory");
    return v;
}

// ---------------------------------------------------------------------------
// bias combine
// ---------------------------------------------------------------------------
__global__ void k_bias(const float* __restrict__ bi0, const float* __restrict__ bh0,
                       const float* __restrict__ bi1, const float* __restrict__ bh1)
{
    int i = blockIdx.x * 256 + threadIdx.x;
    if (i < 2048) {
        g_bias0[i] = bi0[i] + bh0[i];
        g_bias1[i] = bi1[i] + bh1[i];
    }
}

// flag reset before each scan launch (in-graph -> replay-safe)
__global__ void k_rst()
{
    g_flag[threadIdx.x] = 0u;
}

// ---------------------------------------------------------------------------
// embedding gather (float4)
// ---------------------------------------------------------------------------
__global__ void k_embed(const int* __restrict__ ids, const float* __restrict__ emb)
{
    int g  = blockIdx.x * 256 + threadIdx.x;   // 0 .. BT*64-1
    int bt = g >> 6;
    int e4 = g & 63;
    int id = __ldg(ids + bt);
    ((float4*)g_x0)[g] = ((const float4*)emb)[(size_t)id * 64 + e4];
}

// ---------------------------------------------------------------------------
// Input projection SGEMM v3 (f32x2, double-buffered, 128x128 tile) — unchanged
// ---------------------------------------------------------------------------
#define PA 132
#define PB 132
__global__ void __launch_bounds__(256) k_gemm(int layer, int z, const float* __restrict__ Wall)
{
    const float* A    = layer ? g_h0    : g_x0;
    const float* bias = layer ? g_bias1 : g_bias0;
    const int    K    = layer ? 512 : 256;
    const int    KT   = K >> 4;

    const float* W  = Wall + (size_t)z * 1024 * K;
    const float* bz = bias + z * 1024;
    float*       C  = g_xg + (size_t)z * BT * 1024;

    int n0 = blockIdx.x * 128;
    int m0 = blockIdx.y * 128;

    __shared__ __align__(16) float As[2][16 * PA];
    __shared__ __align__(16) float Bs[2][16 * PB];

    int tid = threadIdx.x;
    int tx = tid & 15, ty = tid >> 4;
    int mm = ty * 8, nn = tx * 8;

    int row0 = tid >> 2,          kq = tid & 3;
    int row1 = (tid + 256) >> 2;

    ull acc2[4][8];
#pragma unroll
    for (int i = 0; i < 4; i++)
#pragma unroll
        for (int j = 0; j < 8; j++) acc2[i][j] = 0ull;

    float4 pa0 = *(const float4*)(A + (size_t)(m0 + row0) * K + kq * 4);
    float4 pa1 = *(const float4*)(A + (size_t)(m0 + row1) * K + kq * 4);
    float4 pb0 = *(const float4*)(W + (size_t)(n0 + row0) * K + kq * 4);
    float4 pb1 = *(const float4*)(W + (size_t)(n0 + row1) * K + kq * 4);
    {
        float* asb = As[0];
        asb[(kq * 4 + 0) * PA + row0] = pa0.x;
        asb[(kq * 4 + 1) * PA + row0] = pa0.y;
        asb[(kq * 4 + 2) * PA + row0] = pa0.z;
        asb[(kq * 4 + 3) * PA + row0] = pa0.w;
        asb[(kq * 4 + 0) * PA + row1] = pa1.x;
        asb[(kq * 4 + 1) * PA + row1] = pa1.y;
        asb[(kq * 4 + 2) * PA + row1] = pa1.z;
        asb[(kq * 4 + 3) * PA + row1] = pa1.w;
        float* bsb = Bs[0];
        bsb[(kq * 4 + 0) * PB + row0] = pb0.x;
        bsb[(kq * 4 + 1) * PB + row0] = pb0.y;
        bsb[(kq * 4 + 2) * PB + row0] = pb0.z;
        bsb[(kq * 4 + 3) * PB + row0] = pb0.w;
        bsb[(kq * 4 + 0) * PB + row1] = pb1.x;
        bsb[(kq * 4 + 1) * PB + row1] = pb1.y;
        bsb[(kq * 4 + 2) * PB + row1] = pb1.z;
        bsb[(kq * 4 + 3) * PB + row1] = pb1.w;
    }
    __syncthreads();

    for (int kt = 0; kt < KT; kt++) {
        int cur = kt & 1;
        if (kt + 1 < KT) {
            int kof = (kt + 1) * 16;
            pa0 = *(const float4*)(A + (size_t)(m0 + row0) * K + kof + kq * 4);
            pa1 = *(const float4*)(A + (size_t)(m0 + row1) * K + kof + kq * 4);
            pb0 = *(const float4*)(W + (size_t)(n0 + row0) * K + kof + kq * 4);
            pb1 = *(const float4*)(W + (size_t)(n0 + row1) * K + kof + kq * 4);
        }
        const float* asb = As[cur];
        const float* bsb = Bs[cur];
#pragma unroll
        for (int k = 0; k < 16; k++) {
            ulonglong2 a01 = *(const ulonglong2*)(asb + k * PA + mm);
            ulonglong2 a23 = *(const ulonglong2*)(asb + k * PA + mm + 4);
            float4 b0 = *(const float4*)(bsb + k * PB + nn);
            float4 b1 = *(const float4*)(bsb + k * PB + nn + 4);
            ull av[4] = {a01.x, a01.y, a23.x, a23.y};
            ull bb[8] = {pack2s(b0.x), pack2s(b0.y), pack2s(b0.z), pack2s(b0.w),
                         pack2s(b1.x), pack2s(b1.y), pack2s(b1.z), pack2s(b1.w)};
#pragma unroll
            for (int i = 0; i < 4; i++)
#pragma unroll
                for (int j = 0; j < 8; j++) ffma2(acc2[i][j], av[i], bb[j]);
        }
        if (kt + 1 < KT) {
            float* asn = As[cur ^ 1];
            asn[(kq * 4 + 0) * PA + row0] = pa0.x;
            asn[(kq * 4 + 1) * PA + row0] = pa0.y;
            asn[(kq * 4 + 2) * PA + row0] = pa0.z;
            asn[(kq * 4 + 3) * PA + row0] = pa0.w;
            asn[(kq * 4 + 0) * PA + row1] = pa1.x;
            asn[(kq * 4 + 1) * PA + row1] = pa1.y;
            asn[(kq * 4 + 2) * PA + row1] = pa1.z;
            asn[(kq * 4 + 3) * PA + row1] = pa1.w;
            float* bsn = Bs[cur ^ 1];
            bsn[(kq * 4 + 0) * PB + row0] = pb0.x;
            bsn[(kq * 4 + 1) * PB + row0] = pb0.y;
            bsn[(kq * 4 + 2) * PB + row0] = pb0.z;
            bsn[(kq * 4 + 3) * PB + row0] = pb0.w;
            bsn[(kq * 4 + 0) * PB + row1] = pb1.x;
            bsn[(kq * 4 + 1) * PB + row1] = pb1.y;
            bsn[(kq * 4 + 2) * PB + row1] = pb1.z;
            bsn[(kq * 4 + 3) * PB + row1] = pb1.w;
            __syncthreads();
        }
    }

    float4 bvx0 = *(const float4*)(bz + n0 + nn);
    float4 bvx1 = *(const float4*)(bz + n0 + nn + 4);
#pragma unroll
    for (int ip = 0; ip < 4; ip++) {
        float2 c0 = unpack2(acc2[ip][0]);
        float2 c1 = unpack2(acc2[ip][1]);
        float2 c2 = unpack2(acc2[ip][2]);
        float2 c3 = unpack2(acc2[ip][3]);
        float2 c4 = unpack2(acc2[ip][4]);
        float2 c5 = unpack2(acc2[ip][5]);
        float2 c6 = unpack2(acc2[ip][6]);
        float2 c7 = unpack2(acc2[ip][7]);
        float* r0 = C + (size_t)(m0 + mm + 2 * ip) * 1024 + n0 + nn;
        float* r1 = C + (size_t)(m0 + mm + 2 * ip + 1) * 1024 + n0 + nn;
        float4 oa = {c0.x + bvx0.x, c1.x + bvx0.y, c2.x + bvx0.z, c3.x + bvx0.w};
        float4 ob = {c4.x + bvx1.x, c5.x + bvx1.y, c6.x + bvx1.z, c7.x + bvx1.w};
        *(float4*)(r0) = oa;
        *(float4*)(r0 + 4) = ob;
        float4 oc = {c0.y + bvx0.x, c1.y + bvx0.y, c2.y + bvx0.z, c3.y + bvx0.w};
        float4 od = {c4.y + bvx1.x, c5.y + bvx1.y, c6.y + bvx1.z, c7.y + bvx1.w};
        *(float4*)(r1) = oc;
        *(float4*)(r1 + 4) = od;
    }
}

// ---------------------------------------------------------------------------
// Persistent BiLSTM scan v7: 128 blocks x 512 threads, ONE block/SM.
//   block = dir*64 + btile*16 + utile  (b-tile 32 batches, u-tile 16 units).
//   group = (dir, btile): 16 producer blocks; handshake = per-producer
//   release-flag (value t+1) + 16 parallel acquire-pollers. No atomics.
//   thread: ul = tid&15 (unit), bq = (tid>>4)&7 (4-batch group), ks = tid>>7
//   (k quarter). Epilogue: 1 cell (b,u)/thread, c in register.
//   hout store + xg prefetch in the release->poll shadow; last step no barrier.
// ---------------------------------------------------------------------------
#define KP 260
__global__ void __launch_bounds__(512, 1) k_scan(int layer, const float* __restrict__ Whh_all)
{
    extern __shared__ float sm[];
    float* ws  = sm;                 // [64 rows = 4g x 16u][KP]
    float* hs  = sm + 64 * KP;       // [32 b][KP]; reused as red (8192 floats)
    float* red = hs;

    float* hout = layer ? g_h1 : g_h0;
    int blk = blockIdx.x;
    int dir = blk >> 6;
    int rem = blk & 63;
    int bt  = rem >> 4;              // b-tile 0..3
    int ut  = rem & 15;              // u-tile 0..15 (= producer id)
    int u0  = ut * 16;
    int b0  = bt * 32;
    int grp = dir * 4 + bt;          // 0..7

    int tid = threadIdx.x;
    int ul = tid & 15;
    int bq = (tid >> 4) & 7;
    int ks = tid >> 7;               // 0..3
    int u  = u0 + ul;

    int bo = tid >> 4;               // 0..31 (= ks*8+bq), epilogue batch row
    int bcell = b0 + bo;

    unsigned* myflag = &g_flag[(grp * 16 + ut) * 8];
    unsigned* pollfl = &g_flag[(grp * 16 + (tid & 15)) * 8];

    const float4* W4 = (const float4*)(Whh_all + (size_t)dir * 1024 * 256);
    for (int i = tid; i < 4096; i += 512) {
        int row = i >> 6, k4 = i & 63;
        int g = row >> 4, uu = row & 15;
        int j = g * 256 + u0 + uu;
        *(float4*)(ws + row * KP + k4 * 4) = W4[(size_t)j * 64 + k4];
    }

    float creg = 0.f;

    // xg gates for t = 0 (streaming reads)
    float xpre[4];
    {
        int t0 = dir ? 511 : 0;
        const float* xr = g_xg + ((size_t)dir * BT + (size_t)bcell * 512 + t0) * 1024;
        xpre[0] = __ldcs(xr + u);
        xpre[1] = __ldcs(xr + 256 + u);
        xpre[2] = __ldcs(xr + 512 + u);
        xpre[3] = __ldcs(xr + 768 + u);
    }
    __syncthreads();

    for (int t = 0; t < 512; t++) {
        int t_act = dir ? (511 - t) : t;
        const float* hprev = g_hbuf + ((size_t)dir * 2 + ((t + 1) & 1)) * (Bb * Hh);
        float*       hnext = g_hbuf + ((size_t)dir * 2 + (t & 1)) * (Bb * Hh);

        ull acc2[4][4];
#pragma unroll
        for (int g = 0; g < 4; g++)
#pragma unroll
            for (int i = 0; i < 4; i++) acc2[g][i] = 0ull;

        if (t > 0) {
            // stage hprev (32 x 256) via L2
            const float4* HP4 = (const float4*)hprev;
#pragma unroll
            for (int it = 0; it < 4; it++) {
                int i = tid + it * 512;
                int b = i >> 6, k4 = i & 63;
                float4 v = __ldcg(HP4 + (size_t)(b0 + b) * 64 + k4);
                *(float4*)(hs + b * KP + k4 * 4) = v;
            }
            __syncthreads();
#pragma unroll 8
            for (int kq = 0; kq < 16; kq++) {
                int ko = ks * 64 + kq * 4;
                ulonglong2 wv[4], hv[4];
#pragma unroll
                for (int g = 0; g < 4; g++)
                    wv[g] = *(const ulonglong2*)(ws + (g * 16 + ul) * KP + ko);
#pragma unroll
                for (int i = 0; i < 4; i++)
                    hv[i] = *(const ulonglong2*)(hs + (bq * 4 + i) * KP + ko);
#pragma unroll
                for (int g = 0; g < 4; g++)
#pragma unroll
                    for (int i = 0; i < 4; i++) {
                        ffma2(acc2[g][i], hv[i].x, wv[g].x);
                        ffma2(acc2[g][i], hv[i].y, wv[g].y);
                    }
            }
            __syncthreads();   // hs reads done -> safe to reuse as red
        }

        // k-partial exchange: red[ks][g][b][ul]
#pragma unroll
        for (int g = 0; g < 4; g++)
#pragma unroll
            for (int i = 0; i < 4; i++)
                red[((ks * 4 + g) * 32 + bq * 4 + i) * 16 + ul] = rsum2(acc2[g][i]);
        __syncthreads();

        // epilogue: this thread's single cell (bcell, u)
        float h;
        {
            float gate[4];
#pragma unroll
            for (int g = 0; g < 4; g++) {
                float s = xpre[g];
#pragma unroll
                for (int k = 0; k < 4; k++)
                    s += red[((k * 4 + g) * 32 + bo) * 16 + ul];
                gate[g] = s;
            }
            float c = sigf(gate[1]) * creg + sigf(gate[0]) * tanhf(gate[2]);
            creg = c;
            h = sigf(gate[3]) * tanhf(c);
        }
        size_t btx = (size_t)bcell * 512 + t_act;

        if (t < 511) {
            // publish h, release my flag; shadow work; poll 16 flags
            __stcg(hnext + bcell * Hh + u, h);
            __syncthreads();               // h stores ordered before release
            if (tid == 0) st_release(myflag, (unsigned)(t + 1));
            // barrier shadow: hout store + next xg prefetch
            __stcs(hout + btx * 512 + dir * 256 + u, h);
            {
                int tn = dir ? (510 - t) : (t + 1);
                const float* xr = g_xg + ((size_t)dir * BT + (size_t)bcell * 512 + tn) * 1024;
                xpre[0] = __ldcs(xr + u);
                xpre[1] = __ldcs(xr + 256 + u);
                xpre[2] = __ldcs(xr + 512 + u);
                xpre[3] = __ldcs(xr + 768 + u);
            }
            if (tid < 16) {
                while (ld_acquire(pollfl) < (unsigned)(t + 1)) __nanosleep(16);
            }
            __syncthreads();
        } else {
            __stcs(hout + btx * 512 + dir * 256 + u, h);
        }
    }
}

// ---------------------------------------------------------------------------
// Emissions
// ---------------------------------------------------------------------------
#define PWE 68
__global__ void __launch_bounds__(256) k_emis(const float* __restrict__ fcw,
                                              const float* __restrict__ fcb)
{
    __shared__ __align__(16) float hsm[8 * 512];
    __shared__ __align__(16) float wsm[20 * PWE];

    int bt0 = blockIdx.x * 8;
    int tid = threadIdx.x;

    const float4* H4 = (const float4*)g_h1;
#pragma unroll
    for (int i = tid; i < 1024; i += 256) {
        int r = i >> 7, k4 = i & 127;
        ((float4*)hsm)[r * 128 + k4] = H4[(size_t)(bt0 + r) * 128 + k4];
    }

    int r = tid / 20, c = tid % 20;
    bool act = (tid < 160);
    float acc = 0.f;

    const float4* W4 = (const float4*)fcw;
    for (int cc = 0; cc < 8; cc++) {
        __syncthreads();
        for (int i = tid; i < 320; i += 256) {
            int cw = i >> 4, k4 = i & 15;
            *(float4*)(wsm + cw * PWE + k4 * 4) = W4[(size_t)cw * 128 + cc * 16 + k4];
        }
        __syncthreads();
        if (act) {
#pragma unroll
            for (int k4 = 0; k4 < 16; k4++) {
                float4 h4 = ((const float4*)hsm)[r * 128 + cc * 16 + k4];
                float4 w4 = *(const float4*)(wsm + c * PWE + k4 * 4);
                acc += h4.x * w4.x + h4.y * w4.y + h4.z * w4.z + h4.w * w4.w;
            }
        }
    }
    if (act)
        g_em[(size_t)(bt0 + r) * Cc + c] = acc + __ldg(fcb + c);
}

// ---------------------------------------------------------------------------
// CRF NLL per batch: one warp per batch row.
// ---------------------------------------------------------------------------
__global__ void __launch_bounds__(32) k_crf(const int* __restrict__ labels,
                                            const float* __restrict__ trans,
                                            const float* __restrict__ start,
                                            const float* __restrict__ endt)
{
    int b = blockIdx.x;
    int lane = threadIdx.x;
    const float* em = g_em + (size_t)b * Tt * Cc;
    const int* tag = labels + (size_t)b * Tt;

    float part = 0.f;
    for (int t = lane; t < Tt; t += 32) {
        int tg = __ldg(tag + t);
        part += em[(size_t)t * Cc + tg];
        if (t < Tt - 1) part += __ldg(trans + tg * Cc + __ldg(tag + t + 1));
    }
#pragma unroll
    for (int o = 16; o; o >>= 1) part += __shfl_xor_sync(0xFFFFFFFFu, part, o);
    float num = part;

    int j = lane;
    bool act = (j < Cc);
    float tc[Cc];
#pragma unroll
    for (int i = 0; i < Cc; i++) tc[i] = act ? __ldg(trans + i * Cc + j) : 0.f;

    float alpha = act ? (__ldg(start + j) + em[j]) : -1e30f;
    for (int t = 1; t < Tt; t++) {
        float v[Cc];
        float m = -1e30f;
#pragma unroll
        for (int i = 0; i < Cc; i++) {
            v[i] = __shfl_sync(0xFFFFFFFFu, alpha, i) + tc[i];
            m = fmaxf(m, v[i]);
        }
        float s = 0.f;
#pragma unroll
        for (int i = 0; i < Cc; i++) s += __expf(v[i] - m);
        float e = act ? em[(size_t)t * Cc + j] : 0.f;
        alpha = act ? (m + __logf(s) + e) : -1e30f;
    }

    float av = act ? (alpha + __ldg(endt + j)) : -1e30f;
    float mm = av;
#pragma unroll
    for (int o = 16; o; o >>= 1) mm = fmaxf(mm, __shfl_xor_sync(0xFFFFFFFFu, mm, o));
    float ss = act ? __expf(av - mm) : 0.f;
#pragma unroll
    for (int o = 16; o; o >>= 1) ss += __shfl_xor_sync(0xFFFFFFFFu, ss, o);
    float logZ = mm + __logf(ss);

    if (lane == 0) {
        float g0 = __ldg(start + __ldg(tag + 0)) + __ldg(endt + __ldg(tag + Tt - 1));
        g_lossb[b] = (num + g0) - logZ;
    }
}

// ---------------------------------------------------------------------------
// Final deterministic reduce
// ---------------------------------------------------------------------------
__global__ void k_reduce(float* __restrict__ out)
{
    __shared__ float s[128];
    s[threadIdx.x] = g_lossb[threadIdx.x];
    __syncthreads();
#pragma unroll
    for (int o = 64; o; o >>= 1) {
        if (threadIdx.x < o) s[threadIdx.x] += s[threadIdx.x + o];
        __syncthreads();
    }
    if (threadIdx.x == 0) out[0] = -s[0];
}

// ---------------------------------------------------------------------------
// kernel_launch — 13 nodes; launch #6 = k_scan(L0) for ncu -s 5 -c 1
// ---------------------------------------------------------------------------
extern "C" void kernel_launch(void* const* d_in, const int* in_sizes, int n_in,
                              void* d_out, int out_size)
{
    const int*   ids      = (const int*)d_in[0];
    const int*   labels   = (const int*)d_in[1];
    const float* emb      = (const float*)d_in[2];
    const float* w_ih_l0  = (const float*)d_in[3];
    const float* w_hh_l0  = (const float*)d_in[4];
    const float* b_ih_l0  = (const float*)d_in[5];
    const float* b_hh_l0  = (const float*)d_in[6];
    const float* w_ih_l1  = (const float*)d_in[7];
    const float* w_hh_l1  = (const float*)d_in[8];
    const float* b_ih_l1  = (const float*)d_in[9];
    const float* b_hh_l1  = (const float*)d_in[10];
    const float* fc_w     = (const float*)d_in[11];
    const float* fc_b     = (const float*)d_in[12];
    const float* trans    = (const float*)d_in[13];
    const float* start    = (const float*)d_in[14];
    const float* endt     = (const float*)d_in[15];

    const int scan_smem = (64 * KP + 32 * KP) * (int)sizeof(float);   // 99840 B
    cudaFuncSetAttribute(k_scan, cudaFuncAttributeMaxDynamicSharedMemorySize, scan_smem);

    k_bias<<<8, 256>>>(b_ih_l0, b_hh_l0, b_ih_l1, b_hh_l1);        // 1
    k_embed<<<16384, 256>>>(ids, emb);                              // 2
    k_rst<<<1, 1024>>>();                                           // 3

    // layer 0
    k_gemm<<<dim3(8, 512), 256>>>(0, 0, w_ih_l0);                   // 4
    k_gemm<<<dim3(8, 512), 256>>>(0, 1, w_ih_l0);                   // 5
    k_scan<<<128, 512, scan_smem>>>(0, w_hh_l0);                    // 6  <- profiled

    // layer 1
    k_rst<<<1, 1024>>>();                                           // 7
    k_gemm<<<dim3(8, 512), 256>>>(1, 0, w_ih_l1);                   // 8
    k_gemm<<<dim3(8, 512), 256>>>(1, 1, w_ih_l1);                   // 9
    k_scan<<<128, 512, scan_smem>>>(1, w_hh_l1);                    // 10

    k_emis<<<BT / 8, 256>>>(fc_w, fc_b);                            // 11
    k_crf<<<Bb, 32>>>(labels, trans, start, endt);                  // 12
    k_reduce<<<1, 128>>>((float*)d_out);                            // 13
}